// round 9
// baseline (speedup 1.0000x reference)
#include <cuda_runtime.h>
#include <cstdint>
#include <math.h>

#define H 2048
#define L 350

// -------- persistent scratch (no allocs allowed) --------
__device__ float g_lp[2][L];               // attn logit partials (x-half, h-half)
// unified scratch: [0,2048) x copy | [2048,4096) ctx (atomic, zeroed each replay) |
// [4096,6144) gsum | [6144,12288) gi | [12288,18432) gh
#define SC_VEC   0
#define SC_GSUM  4096
#define SC_GI    6144
#define SC_GH    12288
#define SC_TOTAL 18432
__device__ __align__(16) float g_scr[SC_TOTAL];

__device__ __forceinline__ float warp_sum(float v) {
    #pragma unroll
    for (int o = 16; o > 0; o >>= 1) v += __shfl_xor_sync(0xffffffffu, v, o);
    return v;
}
__device__ __forceinline__ float dot4(float4 a, float4 b) {
    return a.x*b.x + a.y*b.y + a.z*b.z + a.w*b.w;
}

// -------- cp.async plumbing --------
__device__ __forceinline__ void cp16(unsigned int saddr, const void* gaddr) {
    asm volatile("cp.async.cg.shared.global [%0], [%1], 16;" :: "r"(saddr), "l"(gaddr));
}
__device__ __forceinline__ void cp_commit() {
    asm volatile("cp.async.commit_group;");
}
template<int N>
__device__ __forceinline__ void cp_wait() {
    asm volatile("cp.async.wait_group %0;" :: "n"(N));
}

// Issue one 8-row x 512-col tile (16 KB) into smem via cp.async, then commit.
// gbase points at row 0 of this block's 8 rows; stride = row stride in floats.
__device__ __forceinline__ void issue_tile(
    float* wt, const float* gbase, size_t stride, int c0, int tid)
{
    unsigned int sbase = (unsigned int)__cvta_generic_to_shared(wt);
    #pragma unroll
    for (int c = tid; c < 1024; c += 256) {
        int row = c >> 7, off = c & 127;
        cp16(sbase + (unsigned int)(row * 512 + off * 4) * 4,
             gbase + (size_t)row * stride + c0 + off * 4);
    }
    cp_commit();
}

// Global-vector pipelined dot for the small kA GEMV.
template<int NB>
__device__ __forceinline__ float pipelined_dot(
    const float4* __restrict__ W, const float4* __restrict__ V, int lane)
{
    float4 wb[2][4];
    #pragma unroll
    for (int u = 0; u < 4; u++) wb[0][u] = __ldcs(&W[lane + 32*u]);
    float s = 0.f;
    #pragma unroll
    for (int b = 0; b < NB; b++) {
        int cur = b & 1;
        if (b + 1 < NB) {
            #pragma unroll
            for (int u = 0; u < 4; u++)
                wb[cur ^ 1][u] = __ldcs(&W[lane + 32*u + 128*(b+1)]);
        }
        #pragma unroll
        for (int u = 0; u < 4; u++)
            s += dot4(wb[cur][u], V[lane + 32*u + 128*b]);
    }
    return s;
}

// ============================================================
// kA: attn logit partials (700 warps) + zero ctx (16) + copy x (16)
// ============================================================
#define KA_WARPS (700 + 16 + 16)
__global__ __launch_bounds__(256) void kA(
    const float* __restrict__ x, const float* __restrict__ h,
    const float* __restrict__ attn_W)
{
    int warp = (blockIdx.x * blockDim.x + threadIdx.x) >> 5;
    int lane = threadIdx.x & 31;

    if (warp < 700) {
        int row = warp >> 1, half = warp & 1;
        const float4* W = (const float4*)(attn_W + (size_t)row * 2 * H) + half * 512;
        const float4* v = (const float4*)(half ? h : x);
        float s = pipelined_dot<4>(W, v, lane);
        s = warp_sum(s);
        if (lane == 0) g_lp[half][row] = s;
    } else if (warp < 716) {
        int z = warp - 700;                   // zero ctx region [2048,4096)
        *(float4*)(g_scr + 2048 + z * 128 + lane * 4) = make_float4(0.f,0.f,0.f,0.f);
    } else if (warp < KA_WARPS) {
        int z = warp - 716;                   // copy x -> [0,2048)
        int i = z * 32 + lane;
        ((float4*)(g_scr + SC_VEC))[i] = ((const float4*)x)[i];
    }
}

// ============================================================
// kBC: per-block redundant softmax (L2-hot) + ctx partial.
// grid (16, 14): bx -> 128-col chunk, by -> 25-row chunk.
// ============================================================
#define CTX_ROWS 25
__global__ __launch_bounds__(128) void kBC(
    const float* __restrict__ attn_b, const float* __restrict__ enc,
    float* __restrict__ out)
{
    __shared__ float sw[L];
    __shared__ float red[128];
    int tid = threadIdx.x;

    float m = -INFINITY;
    for (int i = tid; i < L; i += 128) {
        float v = g_lp[0][i] + g_lp[1][i] + attn_b[i];
        sw[i] = v; m = fmaxf(m, v);
    }
    red[tid] = m; __syncthreads();
    #pragma unroll
    for (int s = 64; s > 0; s >>= 1) { if (tid < s) red[tid] = fmaxf(red[tid], red[tid+s]); __syncthreads(); }
    float mx = red[0]; __syncthreads();

    float sum = 0.f;
    for (int i = tid; i < L; i += 128) { float e = __expf(sw[i] - mx); sw[i] = e; sum += e; }
    red[tid] = sum; __syncthreads();
    #pragma unroll
    for (int s = 64; s > 0; s >>= 1) { if (tid < s) red[tid] += red[tid+s]; __syncthreads(); }
    float inv = 1.f / red[0]; __syncthreads();
    for (int i = tid; i < L; i += 128) sw[i] *= inv;
    __syncthreads();

    if (blockIdx.x == 0 && blockIdx.y == 0)
        for (int i = tid; i < L; i += 128) out[2*H + i] = sw[i];

    int j  = blockIdx.x * 128 + tid;
    int r0 = blockIdx.y * CTX_ROWS;
    const float* e = enc + (size_t)r0 * H + j;
    float acc = 0.f;
    #pragma unroll
    for (int i = 0; i < CTX_ROWS; ++i)
        acc += sw[r0 + i] * e[(size_t)i * H];
    atomicAdd(&g_scr[SC_VEC + 2048 + j], acc);
}

// ============================================================
// kD: cp.async-staged GEMV.
//   blocks 0..255    -> comb_W @ [x;ctx]  (8 rows/block, 8 stages of 512 cols)
//   blocks 256..1023 -> w_hh @ h          (8 rows/block, 4 stages of 512 cols)
// smem: sv (16 KB max) + 2 x 16 KB weight tiles.
// ============================================================
#define KD_BLOCKS (256 + 768)
__global__ __launch_bounds__(256) void kD(
    const float* __restrict__ h,
    const float* __restrict__ comb_W, const float* __restrict__ w_hh)
{
    __shared__ __align__(16) float sv[4096];
    __shared__ __align__(16) float wt[2][8 * 512];
    int tid  = threadIdx.x;
    int lane = tid & 31;
    int wid  = tid >> 5;
    float4* sv4 = (float4*)sv;

    if (blockIdx.x < 256) {
        const float* gbase = comb_W + (size_t)blockIdx.x * 8 * (2 * H);
        issue_tile(wt[0], gbase, 2 * H, 0,   tid);
        issue_tile(wt[1], gbase, 2 * H, 512, tid);
        // stage [x;ctx] (1024 float4)
        const float4* gv = (const float4*)(g_scr + SC_VEC);
        #pragma unroll
        for (int i = tid; i < 1024; i += 256) sv4[i] = gv[i];

        float s = 0.f;
        #pragma unroll
        for (int k = 0; k < 8; k++) {
            cp_wait<1>(); __syncthreads();
            const float4* w4 = (const float4*)(wt[k & 1] + wid * 512);
            const float4* v4 = (const float4*)sv + k * 128;
            #pragma unroll
            for (int u = 0; u < 4; u++) s += dot4(w4[lane + 32*u], v4[lane + 32*u]);
            __syncthreads();
            if (k + 2 < 8) issue_tile(wt[k & 1], gbase, 2 * H, (k + 2) * 512, tid);
            else cp_commit();
        }
        s = warp_sum(s);
        if (lane == 0) g_scr[SC_GSUM + blockIdx.x * 8 + wid] = s;
    } else {
        int b = blockIdx.x - 256;
        const float* gbase = w_hh + (size_t)b * 8 * H;
        issue_tile(wt[0], gbase, H, 0,   tid);
        issue_tile(wt[1], gbase, H, 512, tid);
        // stage h (512 float4)
        const float4* gv = (const float4*)h;
        #pragma unroll
        for (int i = tid; i < 512; i += 256) sv4[i] = gv[i];

        float s = 0.f;
        #pragma unroll
        for (int k = 0; k < 4; k++) {
            cp_wait<1>(); __syncthreads();
            const float4* w4 = (const float4*)(wt[k & 1] + wid * 512);
            const float4* v4 = (const float4*)sv + k * 128;
            #pragma unroll
            for (int u = 0; u < 4; u++) s += dot4(w4[lane + 32*u], v4[lane + 32*u]);
            __syncthreads();
            if (k + 2 < 4) issue_tile(wt[k & 1], gbase, H, (k + 2) * 512, tid);
            else cp_commit();
        }
        s = warp_sum(s);
        if (lane == 0) g_scr[SC_GH + b * 8 + wid] = s;
    }
}

// ============================================================
// kE: gi = w_ih @ relu(gsum + comb_b), cp.async-staged.
// 768 blocks, 8 rows/block, 4 stages of 512 cols.
// ============================================================
#define KE_BLOCKS 768
__global__ __launch_bounds__(256) void kE(
    const float* __restrict__ w_ih, const float* __restrict__ comb_b)
{
    __shared__ __align__(16) float sv[2048];
    __shared__ __align__(16) float wt[2][8 * 512];
    int tid  = threadIdx.x;
    int lane = tid & 31;
    int wid  = tid >> 5;
    float4* sv4 = (float4*)sv;

    const float* gbase = w_ih + (size_t)blockIdx.x * 8 * H;
    issue_tile(wt[0], gbase, H, 0,   tid);
    issue_tile(wt[1], gbase, H, 512, tid);

    const float4* gs = (const float4*)(g_scr + SC_GSUM);
    const float4* cb = (const float4*)comb_b;
    #pragma unroll
    for (int i = tid; i < 512; i += 256) {
        float4 gv = gs[i], bv = cb[i];
        sv4[i] = make_float4(fmaxf(gv.x + bv.x, 0.f), fmaxf(gv.y + bv.y, 0.f),
                             fmaxf(gv.z + bv.z, 0.f), fmaxf(gv.w + bv.w, 0.f));
    }

    float s = 0.f;
    #pragma unroll
    for (int k = 0; k < 4; k++) {
        cp_wait<1>(); __syncthreads();
        const float4* w4 = (const float4*)(wt[k & 1] + wid * 512);
        const float4* v4 = (const float4*)sv + k * 128;
        #pragma unroll
        for (int u = 0; u < 4; u++) s += dot4(w4[lane + 32*u], v4[lane + 32*u]);
        __syncthreads();
        if (k + 2 < 4) issue_tile(wt[k & 1], gbase, H, (k + 2) * 512, tid);
        else cp_commit();
    }
    s = warp_sum(s);
    if (lane == 0) g_scr[SC_GI + blockIdx.x * 8 + wid] = s;
}

// ============================================================
// kF: GRU gate math + outputs
// ============================================================
__global__ __launch_bounds__(256) void kF(
    const float* __restrict__ h, const float* __restrict__ b_ih,
    const float* __restrict__ b_hh, float* __restrict__ out)
{
    int j = blockIdx.x * blockDim.x + threadIdx.x;
    float hr = g_scr[SC_GH + j]       + b_hh[j];
    float hz = g_scr[SC_GH + j + H]   + b_hh[j + H];
    float hn = g_scr[SC_GH + j + 2*H] + b_hh[j + 2*H];
    float ir = g_scr[SC_GI + j]       + b_ih[j]       + hr;
    float iz = g_scr[SC_GI + j + H]   + b_ih[j + H]   + hz;
    float r  = 1.f / (1.f + __expf(-ir));
    float z  = 1.f / (1.f + __expf(-iz));
    float n  = tanhf(g_scr[SC_GI + j + 2*H] + b_ih[j + 2*H] + r * hn);
    float hv = (1.f - z) * n + z * h[j];
    out[j]     = hv;
    out[H + j] = hv;
}

// ============================================================
extern "C" void kernel_launch(void* const* d_in, const int* in_sizes, int n_in,
                              void* d_out, int out_size)
{
    const float* x      = (const float*)d_in[0];
    const float* h      = (const float*)d_in[1];
    const float* enc    = (const float*)d_in[2];
    const float* attn_W = (const float*)d_in[3];
    const float* attn_b = (const float*)d_in[4];
    const float* comb_W = (const float*)d_in[5];
    const float* comb_b = (const float*)d_in[6];
    const float* w_ih   = (const float*)d_in[7];
    const float* w_hh   = (const float*)d_in[8];
    const float* b_ih   = (const float*)d_in[9];
    const float* b_hh   = (const float*)d_in[10];
    float* out = (float*)d_out;

    kA<<<(KA_WARPS + 7) / 8, 256>>>(x, h, attn_W);
    dim3 cgrid(H / 128, L / CTX_ROWS);
    kBC<<<cgrid, 128>>>(attn_b, enc, out);
    kD<<<KD_BLOCKS, 256>>>(h, comb_W, w_hh);
    kE<<<KE_BLOCKS, 256>>>(w_ih, comb_b);
    kF<<<H / 256, 256>>>(h, b_ih, b_hh, out);
}